// round 1
// baseline (speedup 1.0000x reference)
#include <cuda_runtime.h>
#include <cuda_bf16.h>
#include <math.h>

// ---------------------------------------------------------------------------
// Shapes (fixed for this problem)
// ---------------------------------------------------------------------------
#define T_SEQ   4096
#define C_EMB   768
#define NHEAD   12
#define HDIM    64
#define QKV_N   (3 * C_EMB)   // 2304

// Scratch (no cudaMalloc allowed)
__device__ float g_qkv[T_SEQ * QKV_N];   // [T, 3C]
__device__ float g_att[T_SEQ * C_EMB];   // [T, C]  attention output (pre-proj)

// ---------------------------------------------------------------------------
// Tiled SGEMM: C[M,N] = A[M,K] @ B(+optional transpose) + bias[N]
// BM=BN=64, BK=16, 256 threads, 4x4 microtile per thread.
// TRANSB=false: B is [K,N] row-major (used as x @ W)
// TRANSB=true : B is [N,K] row-major (used as x @ W^T)
// M % 64 == 0, N % 64 == 0, K % 16 == 0 assumed (holds here).
// ---------------------------------------------------------------------------
#define TBM 64
#define TBN 64
#define TBK 16
#define GPAD 4

template <bool TRANSB>
__global__ void gemm_kernel(const float* __restrict__ A,
                            const float* __restrict__ B,
                            const float* __restrict__ bias,
                            float* __restrict__ C,
                            int M, int N, int K)
{
    __shared__ float As[TBK][TBM + GPAD];
    __shared__ float Bs[TBK][TBN + GPAD];

    const int tid = threadIdx.x;        // 0..255
    const int tx = tid & 15;
    const int ty = tid >> 4;
    const int m0 = blockIdx.y * TBM;
    const int n0 = blockIdx.x * TBN;

    float acc[4][4];
#pragma unroll
    for (int i = 0; i < 4; i++)
#pragma unroll
        for (int j = 0; j < 4; j++) acc[i][j] = 0.f;

    for (int k0 = 0; k0 < K; k0 += TBK) {
        // Load A tile: 64 rows x 16 k, one float4 per thread, coalesced on k
        {
            int rr = tid >> 2;            // 0..63
            int kk = (tid & 3) << 2;      // 0,4,8,12
            float4 v = *(const float4*)(A + (size_t)(m0 + rr) * K + k0 + kk);
            As[kk + 0][rr] = v.x; As[kk + 1][rr] = v.y;
            As[kk + 2][rr] = v.z; As[kk + 3][rr] = v.w;
        }
        // Load B tile
        if (!TRANSB) {
            int kk = tid >> 4;            // 0..15
            int nn = (tid & 15) << 2;     // 0..60
            float4 v = *(const float4*)(B + (size_t)(k0 + kk) * N + n0 + nn);
            Bs[kk][nn + 0] = v.x; Bs[kk][nn + 1] = v.y;
            Bs[kk][nn + 2] = v.z; Bs[kk][nn + 3] = v.w;
        } else {
            int nn = tid >> 2;            // 0..63
            int kk = (tid & 3) << 2;      // 0,4,8,12
            float4 v = *(const float4*)(B + (size_t)(n0 + nn) * K + k0 + kk);
            Bs[kk + 0][nn] = v.x; Bs[kk + 1][nn] = v.y;
            Bs[kk + 2][nn] = v.z; Bs[kk + 3][nn] = v.w;
        }
        __syncthreads();

#pragma unroll
        for (int k = 0; k < TBK; k++) {
            float4 a4 = *(const float4*)&As[k][ty << 2];
            float4 b4 = *(const float4*)&Bs[k][tx << 2];
            float a[4] = {a4.x, a4.y, a4.z, a4.w};
            float b[4] = {b4.x, b4.y, b4.z, b4.w};
#pragma unroll
            for (int i = 0; i < 4; i++)
#pragma unroll
                for (int j = 0; j < 4; j++) acc[i][j] += a[i] * b[j];
        }
        __syncthreads();
    }

#pragma unroll
    for (int i = 0; i < 4; i++) {
        int row = m0 + (ty << 2) + i;
        int col = n0 + (tx << 2);
        float4 bv = *(const float4*)(bias + col);
        float4 v = make_float4(acc[i][0] + bv.x, acc[i][1] + bv.y,
                               acc[i][2] + bv.z, acc[i][3] + bv.w);
        *(float4*)(C + (size_t)row * N + col) = v;
    }
}

// ---------------------------------------------------------------------------
// Flash attention, fp32, causal.
// Grid: (T/64, NHEAD). 256 threads. 64x64 q/k tiles, D=64.
// Thread -> row r = tid>>2, and a group of 4 lanes (tid&3) that
//   (a) own score columns c = 4*j + (tid&3)  (bank-conflict-free K reads)
//   (b) own output dims   d = (tid&3)*16 + dd (contiguous, float4 stores)
// Smem: Qs,Ks,Vs,Ps each 64x68 floats -> 69632 B dynamic.
// ---------------------------------------------------------------------------
#define AST 68   // padded row stride in floats

__global__ void attn_kernel(const float* __restrict__ qkv,
                            float* __restrict__ out)
{
    extern __shared__ float sm[];
    float* Qs = sm;
    float* Ks = sm + 64 * AST;
    float* Vs = sm + 2 * 64 * AST;
    float* Ps = sm + 3 * 64 * AST;

    const int tid = threadIdx.x;
    const int h = blockIdx.y;
    const int qb = gridDim.x - 1 - blockIdx.x;   // heavy tiles first
    const int q0 = qb * 64;
    const float scale = 0.125f;                  // 1/sqrt(64)

    // Load + scale Q tile
#pragma unroll
    for (int i = 0; i < 4; i++) {
        int idx = tid + i * 256;                 // 0..1023
        int rr = idx >> 4;
        int d4 = (idx & 15) << 2;
        float4 v = *(const float4*)(qkv + (size_t)(q0 + rr) * QKV_N + h * HDIM + d4);
        float* qp = Qs + rr * AST + d4;
        qp[0] = v.x * scale; qp[1] = v.y * scale;
        qp[2] = v.z * scale; qp[3] = v.w * scale;
    }

    const int r = tid >> 2;
    const int lane4 = tid & 3;
    const int d0 = lane4 << 4;

    float m = -1e30f, l = 0.f;
    float o[16];
#pragma unroll
    for (int i = 0; i < 16; i++) o[i] = 0.f;

    for (int kb = 0; kb <= qb; kb++) {
        const int k0 = kb * 64;
        __syncthreads();   // previous tile fully consumed
#pragma unroll
        for (int i = 0; i < 4; i++) {
            int idx = tid + i * 256;
            int rr = idx >> 4;
            int d4 = (idx & 15) << 2;
            const float* base = qkv + (size_t)(k0 + rr) * QKV_N + h * HDIM + d4;
            float4 kv = *(const float4*)(base + C_EMB);
            float4 vv = *(const float4*)(base + 2 * C_EMB);
            *(float4*)(Ks + rr * AST + d4) = kv;
            *(float4*)(Vs + rr * AST + d4) = vv;
        }
        __syncthreads();

        // S = Q K^T : thread computes 16 scores at cols 4*j+lane4
        float s[16];
#pragma unroll
        for (int j = 0; j < 16; j++) s[j] = 0.f;
#pragma unroll 1
        for (int k = 0; k < 64; k += 4) {
            float4 qv = *(const float4*)(Qs + r * AST + k);
#pragma unroll
            for (int j = 0; j < 16; j++) {
                float4 kv = *(const float4*)(Ks + (4 * j + lane4) * AST + k);
                s[j] += qv.x * kv.x + qv.y * kv.y + qv.z * kv.z + qv.w * kv.w;
            }
        }

        if (kb == qb) {   // diagonal tile: causal mask (k0 == q0)
#pragma unroll
            for (int j = 0; j < 16; j++)
                if (4 * j + lane4 > r) s[j] = -1e30f;
        }

        // Online softmax
        float smax = s[0];
#pragma unroll
        for (int j = 1; j < 16; j++) smax = fmaxf(smax, s[j]);
        smax = fmaxf(smax, __shfl_xor_sync(0xffffffffu, smax, 1));
        smax = fmaxf(smax, __shfl_xor_sync(0xffffffffu, smax, 2));
        float mn = fmaxf(m, smax);
        float corr = __expf(m - mn);
        m = mn;

        float p[16];
        float psum = 0.f;
#pragma unroll
        for (int j = 0; j < 16; j++) { p[j] = __expf(s[j] - mn); psum += p[j]; }
        l = l * corr + psum;
#pragma unroll
        for (int i = 0; i < 16; i++) o[i] *= corr;

#pragma unroll
        for (int j = 0; j < 16; j++) Ps[r * AST + 4 * j + lane4] = p[j];
        __syncthreads();

        // O += P V : thread accumulates dims d0..d0+15 of its row
#pragma unroll 2
        for (int c4 = 0; c4 < 64; c4 += 4) {
            float4 pv = *(const float4*)(Ps + r * AST + c4);
            float pw[4] = {pv.x, pv.y, pv.z, pv.w};
#pragma unroll
            for (int cc = 0; cc < 4; cc++) {
#pragma unroll
                for (int dd = 0; dd < 16; dd += 4) {
                    float4 vv = *(const float4*)(Vs + (c4 + cc) * AST + d0 + dd);
                    o[dd + 0] += pw[cc] * vv.x;
                    o[dd + 1] += pw[cc] * vv.y;
                    o[dd + 2] += pw[cc] * vv.z;
                    o[dd + 3] += pw[cc] * vv.w;
                }
            }
        }
    }

    // Finalize: full row-sum of l across the 4 lanes, normalize, store
    float lsum = l;
    lsum += __shfl_xor_sync(0xffffffffu, lsum, 1);
    lsum += __shfl_xor_sync(0xffffffffu, lsum, 2);
    float inv = 1.f / lsum;

    float* op = out + (size_t)(q0 + r) * C_EMB + h * HDIM + d0;
#pragma unroll
    for (int dd = 0; dd < 16; dd += 4) {
        float4 v = make_float4(o[dd] * inv, o[dd + 1] * inv,
                               o[dd + 2] * inv, o[dd + 3] * inv);
        *(float4*)(op + dd) = v;
    }
}

// ---------------------------------------------------------------------------
// Launch
// ---------------------------------------------------------------------------
extern "C" void kernel_launch(void* const* d_in, const int* in_sizes, int n_in,
                              void* d_out, int out_size)
{
    const float* x      = (const float*)d_in[0];  // [1,4096,768]
    const float* W_attn = (const float*)d_in[1];  // [768,2304]
    const float* b_attn = (const float*)d_in[2];  // [2304]
    const float* W_proj = (const float*)d_in[3];  // [768,768]
    const float* b_proj = (const float*)d_in[4];  // [768]
    float* out = (float*)d_out;                   // [1,4096,768]

    float* qkv = nullptr;
    float* att = nullptr;
    cudaGetSymbolAddress((void**)&qkv, g_qkv);
    cudaGetSymbolAddress((void**)&att, g_att);

    // 1) qkv = x @ W_attn + b_attn
    {
        dim3 grid(QKV_N / TBN, T_SEQ / TBM);
        gemm_kernel<false><<<grid, 256>>>(x, W_attn, b_attn, qkv,
                                          T_SEQ, QKV_N, C_EMB);
    }

    // 2) flash attention
    {
        static int smem_set = 0;
        size_t smem = 4 * 64 * AST * sizeof(float);   // 69632
        cudaFuncSetAttribute(attn_kernel,
                             cudaFuncAttributeMaxDynamicSharedMemorySize,
                             (int)smem);
        (void)smem_set;
        dim3 grid(T_SEQ / 64, NHEAD);
        attn_kernel<<<grid, 256, smem>>>(qkv, att);
    }

    // 3) out = att @ W_proj^T + b_proj
    {
        dim3 grid(C_EMB / TBN, T_SEQ / TBM);
        gemm_kernel<true><<<grid, 256>>>(att, W_proj, b_proj, out,
                                         T_SEQ, C_EMB, C_EMB);
    }
}

// round 2
// speedup vs baseline: 4.0089x; 4.0089x over previous
#include <cuda_runtime.h>
#include <cuda_bf16.h>
#include <math.h>

// ---------------------------------------------------------------------------
// Shapes (fixed for this problem)
// ---------------------------------------------------------------------------
#define T_SEQ   4096
#define C_EMB   768
#define NHEAD   12
#define HDIM    64
#define QKV_N   (3 * C_EMB)   // 2304

// Scratch (no cudaMalloc allowed)
__device__ float g_qkv[T_SEQ * QKV_N];   // [T, 3C]
__device__ float g_att[T_SEQ * C_EMB];   // [T, C]  attention output (pre-proj)

// ---------------------------------------------------------------------------
// Tiled SGEMM: C[M,N] = A[M,K] @ B(+optional transpose) + bias[N]
// ---------------------------------------------------------------------------
#define TBM 64
#define TBN 64
#define TBK 16
#define GPAD 4

template <bool TRANSB>
__global__ void gemm_kernel(const float* __restrict__ A,
                            const float* __restrict__ B,
                            const float* __restrict__ bias,
                            float* __restrict__ C,
                            int M, int N, int K)
{
    __shared__ float As[TBK][TBM + GPAD];
    __shared__ float Bs[TBK][TBN + GPAD];

    const int tid = threadIdx.x;        // 0..255
    const int tx = tid & 15;
    const int ty = tid >> 4;
    const int m0 = blockIdx.y * TBM;
    const int n0 = blockIdx.x * TBN;

    float acc[4][4];
#pragma unroll
    for (int i = 0; i < 4; i++)
#pragma unroll
        for (int j = 0; j < 4; j++) acc[i][j] = 0.f;

    for (int k0 = 0; k0 < K; k0 += TBK) {
        {
            int rr = tid >> 2;
            int kk = (tid & 3) << 2;
            float4 v = *(const float4*)(A + (size_t)(m0 + rr) * K + k0 + kk);
            As[kk + 0][rr] = v.x; As[kk + 1][rr] = v.y;
            As[kk + 2][rr] = v.z; As[kk + 3][rr] = v.w;
        }
        if (!TRANSB) {
            int kk = tid >> 4;
            int nn = (tid & 15) << 2;
            float4 v = *(const float4*)(B + (size_t)(k0 + kk) * N + n0 + nn);
            Bs[kk][nn + 0] = v.x; Bs[kk][nn + 1] = v.y;
            Bs[kk][nn + 2] = v.z; Bs[kk][nn + 3] = v.w;
        } else {
            int nn = tid >> 2;
            int kk = (tid & 3) << 2;
            float4 v = *(const float4*)(B + (size_t)(n0 + nn) * K + k0 + kk);
            Bs[kk + 0][nn] = v.x; Bs[kk + 1][nn] = v.y;
            Bs[kk + 2][nn] = v.z; Bs[kk + 3][nn] = v.w;
        }
        __syncthreads();

#pragma unroll
        for (int k = 0; k < TBK; k++) {
            float4 a4 = *(const float4*)&As[k][ty << 2];
            float4 b4 = *(const float4*)&Bs[k][tx << 2];
            float a[4] = {a4.x, a4.y, a4.z, a4.w};
            float b[4] = {b4.x, b4.y, b4.z, b4.w};
#pragma unroll
            for (int i = 0; i < 4; i++)
#pragma unroll
                for (int j = 0; j < 4; j++) acc[i][j] += a[i] * b[j];
        }
        __syncthreads();
    }

#pragma unroll
    for (int i = 0; i < 4; i++) {
        int row = m0 + (ty << 2) + i;
        int col = n0 + (tx << 2);
        float4 bv = *(const float4*)(bias + col);
        float4 v = make_float4(acc[i][0] + bv.x, acc[i][1] + bv.y,
                               acc[i][2] + bv.z, acc[i][3] + bv.w);
        *(float4*)(C + (size_t)row * N + col) = v;
    }
}

// ---------------------------------------------------------------------------
// Flash attention with tf32 mma.sync (m16n8k8), causal.
// Grid: (T/64, NHEAD). 128 threads = 4 warps, each warp owns 16 q-rows.
// Q fragments converted to tf32 once and held in registers; Q smem region is
// reused for P. K stride 68 (conflict-free B-frag loads), V stride 72.
// ---------------------------------------------------------------------------
#define KST 68   // K / P / Q staging stride (floats)
#define VST 72   // V stride (floats)

__device__ __forceinline__ unsigned f2tf(float x) {
    unsigned r;
    asm("cvt.rna.tf32.f32 %0, %1;" : "=r"(r) : "f"(x));
    return r;
}

__device__ __forceinline__ void mma_tf32(float c[4],
                                         const unsigned a[4],
                                         unsigned b0, unsigned b1) {
    asm volatile(
        "mma.sync.aligned.m16n8k8.row.col.f32.tf32.tf32.f32 "
        "{%0,%1,%2,%3}, {%4,%5,%6,%7}, {%8,%9}, {%0,%1,%2,%3};"
        : "+f"(c[0]), "+f"(c[1]), "+f"(c[2]), "+f"(c[3])
        : "r"(a[0]), "r"(a[1]), "r"(a[2]), "r"(a[3]), "r"(b0), "r"(b1));
}

__global__ void __launch_bounds__(128)
attn_kernel(const float* __restrict__ qkv, float* __restrict__ out)
{
    extern __shared__ float sm[];
    float* Qs = sm;                 // 64 x KST  (later reused as Ps)
    float* Ps = sm;
    float* Ks = sm + 64 * KST;      // 64 x KST
    float* Vs = sm + 2 * 64 * KST;  // 64 x VST

    const int tid  = threadIdx.x;
    const int w    = tid >> 5;          // warp 0..3 -> q rows [16w,16w+16)
    const int lane = tid & 31;
    const int g    = lane >> 2;         // 0..7
    const int t    = lane & 3;          // 0..3
    const int h    = blockIdx.y;
    const int qb   = gridDim.x - 1 - blockIdx.x;   // heavy tiles first
    const int q0   = qb * 64;
    const float scale = 0.125f;

    // ---- Stage Q (scaled, tf32-converted) into smem ----
#pragma unroll
    for (int i = 0; i < 8; i++) {
        int idx = tid + i * 128;            // 0..1023 float4 slots
        int rr = idx >> 4;
        int d4 = (idx & 15) << 2;
        float4 v = *(const float4*)(qkv + (size_t)(q0 + rr) * QKV_N + h * HDIM + d4);
        float* qp = Qs + rr * KST + d4;
        qp[0] = __uint_as_float(f2tf(v.x * scale));
        qp[1] = __uint_as_float(f2tf(v.y * scale));
        qp[2] = __uint_as_float(f2tf(v.z * scale));
        qp[3] = __uint_as_float(f2tf(v.w * scale));
    }
    __syncthreads();

    // ---- Q fragments (kept in registers for the whole kernel) ----
    unsigned qf[8][4];
    {
        const float* qa = Qs + (16 * w + g) * KST;
        const float* qb2 = qa + 8 * KST;
#pragma unroll
        for (int ks = 0; ks < 8; ks++) {
            qf[ks][0] = __float_as_uint(qa [8 * ks + t]);
            qf[ks][1] = __float_as_uint(qb2[8 * ks + t]);
            qf[ks][2] = __float_as_uint(qa [8 * ks + t + 4]);
            qf[ks][3] = __float_as_uint(qb2[8 * ks + t + 4]);
        }
    }

    float o[8][4];
#pragma unroll
    for (int nb = 0; nb < 8; nb++)
#pragma unroll
        for (int j = 0; j < 4; j++) o[nb][j] = 0.f;

    float mA = -1e30f, mB = -1e30f, lA = 0.f, lB = 0.f;

    for (int kb = 0; kb <= qb; kb++) {
        const int k0 = kb * 64;
        __syncthreads();   // prev-iter P/V reads done; Q frags loaded (iter 0)

        // ---- Load K,V tile (tf32-converted) ----
#pragma unroll
        for (int i = 0; i < 8; i++) {
            int idx = tid + i * 128;
            int rr = idx >> 4;
            int d4 = (idx & 15) << 2;
            const float* base = qkv + (size_t)(k0 + rr) * QKV_N + h * HDIM + d4;
            float4 kv = *(const float4*)(base + C_EMB);
            float4 vv = *(const float4*)(base + 2 * C_EMB);
            float* kp = Ks + rr * KST + d4;
            kp[0] = __uint_as_float(f2tf(kv.x));
            kp[1] = __uint_as_float(f2tf(kv.y));
            kp[2] = __uint_as_float(f2tf(kv.z));
            kp[3] = __uint_as_float(f2tf(kv.w));
            float* vp = Vs + rr * VST + d4;
            vp[0] = __uint_as_float(f2tf(vv.x));
            vp[1] = __uint_as_float(f2tf(vv.y));
            vp[2] = __uint_as_float(f2tf(vv.z));
            vp[3] = __uint_as_float(f2tf(vv.w));
        }
        __syncthreads();

        // ---- S = Q K^T ----
        float s[8][4];
#pragma unroll
        for (int nb = 0; nb < 8; nb++)
#pragma unroll
            for (int j = 0; j < 4; j++) s[nb][j] = 0.f;

#pragma unroll
        for (int ks = 0; ks < 8; ks++) {
#pragma unroll
            for (int nb = 0; nb < 8; nb++) {
                const float* kp = Ks + (8 * nb + g) * KST + 8 * ks + t;
                unsigned b0 = __float_as_uint(kp[0]);
                unsigned b1 = __float_as_uint(kp[4]);
                mma_tf32(s[nb], qf[ks], b0, b1);
            }
        }

        // ---- Causal mask on diagonal tile ----
        if (kb == qb) {
            const int rowA = 16 * w + g;
            const int rowB = rowA + 8;
#pragma unroll
            for (int nb = 0; nb < 8; nb++) {
                int c0 = 8 * nb + 2 * t;
                if (c0     > rowA) s[nb][0] = -1e30f;
                if (c0 + 1 > rowA) s[nb][1] = -1e30f;
                if (c0     > rowB) s[nb][2] = -1e30f;
                if (c0 + 1 > rowB) s[nb][3] = -1e30f;
            }
        }

        // ---- Online softmax (rows g and g+8 of this warp's 16) ----
        float mxA = s[0][0], mxB = s[0][2];
#pragma unroll
        for (int nb = 0; nb < 8; nb++) {
            mxA = fmaxf(mxA, fmaxf(s[nb][0], s[nb][1]));
            mxB = fmaxf(mxB, fmaxf(s[nb][2], s[nb][3]));
        }
        mxA = fmaxf(mxA, __shfl_xor_sync(0xffffffffu, mxA, 1));
        mxA = fmaxf(mxA, __shfl_xor_sync(0xffffffffu, mxA, 2));
        mxB = fmaxf(mxB, __shfl_xor_sync(0xffffffffu, mxB, 1));
        mxB = fmaxf(mxB, __shfl_xor_sync(0xffffffffu, mxB, 2));

        float nmA = fmaxf(mA, mxA), nmB = fmaxf(mB, mxB);
        float corrA = __expf(mA - nmA), corrB = __expf(mB - nmB);
        mA = nmA; mB = nmB;
        lA *= corrA; lB *= corrB;

#pragma unroll
        for (int nb = 0; nb < 8; nb++) {
            s[nb][0] = __expf(s[nb][0] - mA); lA += s[nb][0];
            s[nb][1] = __expf(s[nb][1] - mA); lA += s[nb][1];
            s[nb][2] = __expf(s[nb][2] - mB); lB += s[nb][2];
            s[nb][3] = __expf(s[nb][3] - mB); lB += s[nb][3];
            o[nb][0] *= corrA; o[nb][1] *= corrA;
            o[nb][2] *= corrB; o[nb][3] *= corrB;
        }

        // ---- Write P (tf32) to smem (reuses Q region) ----
        {
            const int rowA = 16 * w + g;
#pragma unroll
            for (int nb = 0; nb < 8; nb++) {
                int c0 = 8 * nb + 2 * t;
                uint2 pa = make_uint2(f2tf(s[nb][0]), f2tf(s[nb][1]));
                uint2 pb = make_uint2(f2tf(s[nb][2]), f2tf(s[nb][3]));
                *(uint2*)(Ps + rowA * KST + c0)       = pa;
                *(uint2*)(Ps + (rowA + 8) * KST + c0) = pb;
            }
        }
        __syncthreads();

        // ---- O += P V ----
#pragma unroll
        for (int ks = 0; ks < 8; ks++) {
            const float* pa = Ps + (16 * w + g) * KST + 8 * ks + t;
            const float* pb = pa + 8 * KST;
            unsigned af[4];
            af[0] = __float_as_uint(pa[0]);
            af[1] = __float_as_uint(pb[0]);
            af[2] = __float_as_uint(pa[4]);
            af[3] = __float_as_uint(pb[4]);
#pragma unroll
            for (int nb = 0; nb < 8; nb++) {
                const float* vp0 = Vs + (8 * ks + t) * VST + 8 * nb + g;
                unsigned b0 = __float_as_uint(vp0[0]);
                unsigned b1 = __float_as_uint(vp0[4 * VST]);
                mma_tf32(o[nb], af, b0, b1);
            }
        }
    }

    // ---- Finalize ----
    lA += __shfl_xor_sync(0xffffffffu, lA, 1);
    lA += __shfl_xor_sync(0xffffffffu, lA, 2);
    lB += __shfl_xor_sync(0xffffffffu, lB, 1);
    lB += __shfl_xor_sync(0xffffffffu, lB, 2);
    float invA = 1.f / lA, invB = 1.f / lB;

    const int rowA = q0 + 16 * w + g;
#pragma unroll
    for (int nb = 0; nb < 8; nb++) {
        int col = h * HDIM + 8 * nb + 2 * t;
        float2 va = make_float2(o[nb][0] * invA, o[nb][1] * invA);
        float2 vb = make_float2(o[nb][2] * invB, o[nb][3] * invB);
        *(float2*)(out + (size_t)rowA * C_EMB + col)       = va;
        *(float2*)(out + (size_t)(rowA + 8) * C_EMB + col) = vb;
    }
}

// ---------------------------------------------------------------------------
// Launch
// ---------------------------------------------------------------------------
extern "C" void kernel_launch(void* const* d_in, const int* in_sizes, int n_in,
                              void* d_out, int out_size)
{
    const float* x      = (const float*)d_in[0];
    const float* W_attn = (const float*)d_in[1];
    const float* b_attn = (const float*)d_in[2];
    const float* W_proj = (const float*)d_in[3];
    const float* b_proj = (const float*)d_in[4];
    float* out = (float*)d_out;

    float* qkv = nullptr;
    float* att = nullptr;
    cudaGetSymbolAddress((void**)&qkv, g_qkv);
    cudaGetSymbolAddress((void**)&att, g_att);

    // 1) qkv = x @ W_attn + b_attn
    {
        dim3 grid(QKV_N / TBN, T_SEQ / TBM);
        gemm_kernel<false><<<grid, 256>>>(x, W_attn, b_attn, qkv,
                                          T_SEQ, QKV_N, C_EMB);
    }

    // 2) flash attention (tf32 mma)
    {
        size_t smem = (size_t)(2 * 64 * KST + 64 * VST) * sizeof(float); // 53248
        cudaFuncSetAttribute(attn_kernel,
                             cudaFuncAttributeMaxDynamicSharedMemorySize,
                             (int)smem);
        dim3 grid(T_SEQ / 64, NHEAD);
        attn_kernel<<<grid, 128, smem>>>(qkv, att);
    }

    // 3) out = att @ W_proj^T + b_proj
    {
        dim3 grid(C_EMB / TBN, T_SEQ / TBM);
        gemm_kernel<true><<<grid, 256>>>(att, W_proj, b_proj, out,
                                         T_SEQ, C_EMB, C_EMB);
    }
}

// round 3
// speedup vs baseline: 7.0387x; 1.7558x over previous
#include <cuda_runtime.h>
#include <cuda_bf16.h>
#include <math.h>

// ---------------------------------------------------------------------------
// Shapes (fixed for this problem)
// ---------------------------------------------------------------------------
#define T_SEQ   4096
#define C_EMB   768
#define NHEAD   12
#define HDIM    64
#define QKV_N   (3 * C_EMB)   // 2304

// Scratch (no cudaMalloc allowed)
__device__ float g_qkv[T_SEQ * QKV_N];    // [T, 3C]
__device__ float g_att[T_SEQ * C_EMB];    // [T, C]
__device__ float g_wpt[C_EMB * C_EMB];    // W_proj^T

// ---------------------------------------------------------------------------
// tf32 helpers
// ---------------------------------------------------------------------------
__device__ __forceinline__ unsigned f2tf(float x) {
    unsigned r;
    asm("cvt.rna.tf32.f32 %0, %1;" : "=r"(r) : "f"(x));
    return r;
}

__device__ __forceinline__ void mma_tf32(float c[4],
                                         const unsigned a[4],
                                         unsigned b0, unsigned b1) {
    asm volatile(
        "mma.sync.aligned.m16n8k8.row.col.f32.tf32.tf32.f32 "
        "{%0,%1,%2,%3}, {%4,%5,%6,%7}, {%8,%9}, {%0,%1,%2,%3};"
        : "+f"(c[0]), "+f"(c[1]), "+f"(c[2]), "+f"(c[3])
        : "r"(a[0]), "r"(a[1]), "r"(a[2]), "r"(a[3]), "r"(b0), "r"(b1));
}

// ---------------------------------------------------------------------------
// W_proj transpose: g_wpt[k][n] = W_proj[n][k]   (768x768)
// ---------------------------------------------------------------------------
__global__ void transpose768(const float* __restrict__ in,
                             float* __restrict__ out)
{
    __shared__ float t[32][33];
    int x = blockIdx.x * 32 + threadIdx.x;
    int y0 = blockIdx.y * 32;
#pragma unroll
    for (int j = 0; j < 32; j += 8)
        t[threadIdx.y + j][threadIdx.x] = in[(size_t)(y0 + threadIdx.y + j) * C_EMB + x];
    __syncthreads();
    int xo = blockIdx.y * 32 + threadIdx.x;
    int yo0 = blockIdx.x * 32;
#pragma unroll
    for (int j = 0; j < 32; j += 8)
        out[(size_t)(yo0 + threadIdx.y + j) * C_EMB + xo] = t[threadIdx.x][threadIdx.y + j];
}

// ---------------------------------------------------------------------------
// tf32 GEMM: C[M,N] = A[M,K] @ B[K,N] + bias[N]
// 128x128x16 CTA tile, 256 threads / 8 warps, warp tile 32x64.
// As: [m][k] stride 20 (conflict-free frag loads: banks 20g+t distinct)
// Bs: [k][n] stride 136 (banks 8t+g distinct)
// Register-staged prefetch pipeline hides gmem latency behind MMA.
// Requires M%128==0, N%128==0, K%16==0.
// ---------------------------------------------------------------------------
#define GBM 128
#define GBN 128
#define GBK 16
#define AS_ST 20
#define BS_ST 136

__global__ void __launch_bounds__(256)
gemm_tf32(const float* __restrict__ A, const float* __restrict__ B,
          const float* __restrict__ bias, float* __restrict__ C,
          int M, int N, int K)
{
    __shared__ float As[GBM][AS_ST];
    __shared__ float Bs[GBK][BS_ST];

    const int tid  = threadIdx.x;
    const int w    = tid >> 5;
    const int lane = tid & 31;
    const int g    = lane >> 2;
    const int t    = lane & 3;
    const int wm   = (w & 3) * 32;       // warp row offset
    const int wn   = (w >> 2) * 64;      // warp col offset
    const int m0   = blockIdx.y * GBM;
    const int n0   = blockIdx.x * GBN;

    // Gmem load thread mapping
    const int a_rr = tid >> 2;           // + 64*i, i in {0,1}
    const int a_kc = (tid & 3) << 2;
    const int b_kk = tid >> 5;           // + 8*i
    const int b_nc = (tid & 31) << 2;

    float4 ra[2], rb[2];

    auto load_tile = [&](int k0) {
#pragma unroll
        for (int i = 0; i < 2; i++) {
            ra[i] = *(const float4*)(A + (size_t)(m0 + a_rr + 64 * i) * K + k0 + a_kc);
            rb[i] = *(const float4*)(B + (size_t)(k0 + b_kk + 8 * i) * N + n0 + b_nc);
        }
    };
    auto store_tile = [&]() {
#pragma unroll
        for (int i = 0; i < 2; i++) {
            float4 va = make_float4(__uint_as_float(f2tf(ra[i].x)),
                                    __uint_as_float(f2tf(ra[i].y)),
                                    __uint_as_float(f2tf(ra[i].z)),
                                    __uint_as_float(f2tf(ra[i].w)));
            *(float4*)&As[a_rr + 64 * i][a_kc] = va;
            float4 vb = make_float4(__uint_as_float(f2tf(rb[i].x)),
                                    __uint_as_float(f2tf(rb[i].y)),
                                    __uint_as_float(f2tf(rb[i].z)),
                                    __uint_as_float(f2tf(rb[i].w)));
            *(float4*)&Bs[b_kk + 8 * i][b_nc] = vb;
        }
    };

    float acc[2][8][4];
#pragma unroll
    for (int mi = 0; mi < 2; mi++)
#pragma unroll
        for (int ni = 0; ni < 8; ni++)
#pragma unroll
            for (int j = 0; j < 4; j++) acc[mi][ni][j] = 0.f;

    load_tile(0);
    store_tile();
    __syncthreads();

    for (int k0 = 0; k0 < K; k0 += GBK) {
        const bool more = (k0 + GBK) < K;
        if (more) load_tile(k0 + GBK);

#pragma unroll
        for (int ks = 0; ks < 2; ks++) {
            unsigned af[2][4];
#pragma unroll
            for (int mi = 0; mi < 2; mi++) {
                const float* ap = &As[wm + 16 * mi + g][8 * ks + t];
                af[mi][0] = __float_as_uint(ap[0]);
                af[mi][1] = __float_as_uint(ap[8 * AS_ST]);
                af[mi][2] = __float_as_uint(ap[4]);
                af[mi][3] = __float_as_uint(ap[8 * AS_ST + 4]);
            }
#pragma unroll
            for (int ni = 0; ni < 8; ni++) {
                const float* bp = &Bs[8 * ks + t][wn + 8 * ni + g];
                unsigned b0 = __float_as_uint(bp[0]);
                unsigned b1 = __float_as_uint(bp[4 * BS_ST]);
                mma_tf32(acc[0][ni], af[0], b0, b1);
                mma_tf32(acc[1][ni], af[1], b0, b1);
            }
        }
        __syncthreads();
        if (more) { store_tile(); __syncthreads(); }
    }

    // Epilogue: add bias, store
#pragma unroll
    for (int mi = 0; mi < 2; mi++) {
        int row = m0 + wm + 16 * mi + g;
#pragma unroll
        for (int ni = 0; ni < 8; ni++) {
            int col = n0 + wn + 8 * ni + 2 * t;
            float2 bv = *(const float2*)(bias + col);
            float2 v0 = make_float2(acc[mi][ni][0] + bv.x, acc[mi][ni][1] + bv.y);
            float2 v1 = make_float2(acc[mi][ni][2] + bv.x, acc[mi][ni][3] + bv.y);
            *(float2*)(C + (size_t)row * N + col)       = v0;
            *(float2*)(C + (size_t)(row + 8) * N + col) = v1;
        }
    }
}

// ---------------------------------------------------------------------------
// Flash attention with tf32 mma.sync (m16n8k8), causal. (unchanged from R2)
// ---------------------------------------------------------------------------
#define KST 68
#define VST 72

__global__ void __launch_bounds__(128)
attn_kernel(const float* __restrict__ qkv, float* __restrict__ out)
{
    extern __shared__ float sm[];
    float* Qs = sm;
    float* Ps = sm;
    float* Ks = sm + 64 * KST;
    float* Vs = sm + 2 * 64 * KST;

    const int tid  = threadIdx.x;
    const int w    = tid >> 5;
    const int lane = tid & 31;
    const int g    = lane >> 2;
    const int t    = lane & 3;
    const int h    = blockIdx.y;
    const int qb   = gridDim.x - 1 - blockIdx.x;
    const int q0   = qb * 64;
    const float scale = 0.125f;

#pragma unroll
    for (int i = 0; i < 8; i++) {
        int idx = tid + i * 128;
        int rr = idx >> 4;
        int d4 = (idx & 15) << 2;
        float4 v = *(const float4*)(qkv + (size_t)(q0 + rr) * QKV_N + h * HDIM + d4);
        float* qp = Qs + rr * KST + d4;
        qp[0] = __uint_as_float(f2tf(v.x * scale));
        qp[1] = __uint_as_float(f2tf(v.y * scale));
        qp[2] = __uint_as_float(f2tf(v.z * scale));
        qp[3] = __uint_as_float(f2tf(v.w * scale));
    }
    __syncthreads();

    unsigned qf[8][4];
    {
        const float* qa = Qs + (16 * w + g) * KST;
        const float* qb2 = qa + 8 * KST;
#pragma unroll
        for (int ks = 0; ks < 8; ks++) {
            qf[ks][0] = __float_as_uint(qa [8 * ks + t]);
            qf[ks][1] = __float_as_uint(qb2[8 * ks + t]);
            qf[ks][2] = __float_as_uint(qa [8 * ks + t + 4]);
            qf[ks][3] = __float_as_uint(qb2[8 * ks + t + 4]);
        }
    }

    float o[8][4];
#pragma unroll
    for (int nb = 0; nb < 8; nb++)
#pragma unroll
        for (int j = 0; j < 4; j++) o[nb][j] = 0.f;

    float mA = -1e30f, mB = -1e30f, lA = 0.f, lB = 0.f;

    for (int kb = 0; kb <= qb; kb++) {
        const int k0 = kb * 64;
        __syncthreads();

#pragma unroll
        for (int i = 0; i < 8; i++) {
            int idx = tid + i * 128;
            int rr = idx >> 4;
            int d4 = (idx & 15) << 2;
            const float* base = qkv + (size_t)(k0 + rr) * QKV_N + h * HDIM + d4;
            float4 kv = *(const float4*)(base + C_EMB);
            float4 vv = *(const float4*)(base + 2 * C_EMB);
            float* kp = Ks + rr * KST + d4;
            kp[0] = __uint_as_float(f2tf(kv.x));
            kp[1] = __uint_as_float(f2tf(kv.y));
            kp[2] = __uint_as_float(f2tf(kv.z));
            kp[3] = __uint_as_float(f2tf(kv.w));
            float* vp = Vs + rr * VST + d4;
            vp[0] = __uint_as_float(f2tf(vv.x));
            vp[1] = __uint_as_float(f2tf(vv.y));
            vp[2] = __uint_as_float(f2tf(vv.z));
            vp[3] = __uint_as_float(f2tf(vv.w));
        }
        __syncthreads();

        float s[8][4];
#pragma unroll
        for (int nb = 0; nb < 8; nb++)
#pragma unroll
            for (int j = 0; j < 4; j++) s[nb][j] = 0.f;

#pragma unroll
        for (int ks = 0; ks < 8; ks++) {
#pragma unroll
            for (int nb = 0; nb < 8; nb++) {
                const float* kp = Ks + (8 * nb + g) * KST + 8 * ks + t;
                unsigned b0 = __float_as_uint(kp[0]);
                unsigned b1 = __float_as_uint(kp[4]);
                mma_tf32(s[nb], qf[ks], b0, b1);
            }
        }

        if (kb == qb) {
            const int rowA = 16 * w + g;
            const int rowB = rowA + 8;
#pragma unroll
            for (int nb = 0; nb < 8; nb++) {
                int c0 = 8 * nb + 2 * t;
                if (c0     > rowA) s[nb][0] = -1e30f;
                if (c0 + 1 > rowA) s[nb][1] = -1e30f;
                if (c0     > rowB) s[nb][2] = -1e30f;
                if (c0 + 1 > rowB) s[nb][3] = -1e30f;
            }
        }

        float mxA = s[0][0], mxB = s[0][2];
#pragma unroll
        for (int nb = 0; nb < 8; nb++) {
            mxA = fmaxf(mxA, fmaxf(s[nb][0], s[nb][1]));
            mxB = fmaxf(mxB, fmaxf(s[nb][2], s[nb][3]));
        }
        mxA = fmaxf(mxA, __shfl_xor_sync(0xffffffffu, mxA, 1));
        mxA = fmaxf(mxA, __shfl_xor_sync(0xffffffffu, mxA, 2));
        mxB = fmaxf(mxB, __shfl_xor_sync(0xffffffffu, mxB, 1));
        mxB = fmaxf(mxB, __shfl_xor_sync(0xffffffffu, mxB, 2));

        float nmA = fmaxf(mA, mxA), nmB = fmaxf(mB, mxB);
        float corrA = __expf(mA - nmA), corrB = __expf(mB - nmB);
        mA = nmA; mB = nmB;
        lA *= corrA; lB *= corrB;

#pragma unroll
        for (int nb = 0; nb < 8; nb++) {
            s[nb][0] = __expf(s[nb][0] - mA); lA += s[nb][0];
            s[nb][1] = __expf(s[nb][1] - mA); lA += s[nb][1];
            s[nb][2] = __expf(s[nb][2] - mB); lB += s[nb][2];
            s[nb][3] = __expf(s[nb][3] - mB); lB += s[nb][3];
            o[nb][0] *= corrA; o[nb][1] *= corrA;
            o[nb][2] *= corrB; o[nb][3] *= corrB;
        }

        {
            const int rowA = 16 * w + g;
#pragma unroll
            for (int nb = 0; nb < 8; nb++) {
                int c0 = 8 * nb + 2 * t;
                uint2 pa = make_uint2(f2tf(s[nb][0]), f2tf(s[nb][1]));
                uint2 pb = make_uint2(f2tf(s[nb][2]), f2tf(s[nb][3]));
                *(uint2*)(Ps + rowA * KST + c0)       = pa;
                *(uint2*)(Ps + (rowA + 8) * KST + c0) = pb;
            }
        }
        __syncthreads();

#pragma unroll
        for (int ks = 0; ks < 8; ks++) {
            const float* pa = Ps + (16 * w + g) * KST + 8 * ks + t;
            const float* pb = pa + 8 * KST;
            unsigned af[4];
            af[0] = __float_as_uint(pa[0]);
            af[1] = __float_as_uint(pb[0]);
            af[2] = __float_as_uint(pa[4]);
            af[3] = __float_as_uint(pb[4]);
#pragma unroll
            for (int nb = 0; nb < 8; nb++) {
                const float* vp0 = Vs + (8 * ks + t) * VST + 8 * nb + g;
                unsigned b0 = __float_as_uint(vp0[0]);
                unsigned b1 = __float_as_uint(vp0[4 * VST]);
                mma_tf32(o[nb], af, b0, b1);
            }
        }
    }

    lA += __shfl_xor_sync(0xffffffffu, lA, 1);
    lA += __shfl_xor_sync(0xffffffffu, lA, 2);
    lB += __shfl_xor_sync(0xffffffffu, lB, 1);
    lB += __shfl_xor_sync(0xffffffffu, lB, 2);
    float invA = 1.f / lA, invB = 1.f / lB;

    const int rowA = q0 + 16 * w + g;
#pragma unroll
    for (int nb = 0; nb < 8; nb++) {
        int col = h * HDIM + 8 * nb + 2 * t;
        float2 va = make_float2(o[nb][0] * invA, o[nb][1] * invA);
        float2 vb = make_float2(o[nb][2] * invB, o[nb][3] * invB);
        *(float2*)(out + (size_t)rowA * C_EMB + col)       = va;
        *(float2*)(out + (size_t)(rowA + 8) * C_EMB + col) = vb;
    }
}

// ---------------------------------------------------------------------------
// Launch
// ---------------------------------------------------------------------------
extern "C" void kernel_launch(void* const* d_in, const int* in_sizes, int n_in,
                              void* d_out, int out_size)
{
    const float* x      = (const float*)d_in[0];
    const float* W_attn = (const float*)d_in[1];
    const float* b_attn = (const float*)d_in[2];
    const float* W_proj = (const float*)d_in[3];
    const float* b_proj = (const float*)d_in[4];
    float* out = (float*)d_out;

    float* qkv = nullptr;
    float* att = nullptr;
    float* wpt = nullptr;
    cudaGetSymbolAddress((void**)&qkv, g_qkv);
    cudaGetSymbolAddress((void**)&att, g_att);
    cudaGetSymbolAddress((void**)&wpt, g_wpt);

    // 0) W_proj^T
    {
        dim3 grid(C_EMB / 32, C_EMB / 32);
        transpose768<<<grid, dim3(32, 8)>>>(W_proj, wpt);
    }

    // 1) qkv = x @ W_attn + b_attn  (tf32 tensor cores)
    {
        dim3 grid(QKV_N / GBN, T_SEQ / GBM);
        gemm_tf32<<<grid, 256>>>(x, W_attn, b_attn, qkv, T_SEQ, QKV_N, C_EMB);
    }

    // 2) flash attention (tf32 mma)
    {
        size_t smem = (size_t)(2 * 64 * KST + 64 * VST) * sizeof(float);
        cudaFuncSetAttribute(attn_kernel,
                             cudaFuncAttributeMaxDynamicSharedMemorySize,
                             (int)smem);
        dim3 grid(T_SEQ / 64, NHEAD);
        attn_kernel<<<grid, 128, smem>>>(qkv, att);
    }

    // 3) out = att @ W_proj^T + b_proj  (tf32 tensor cores)
    {
        dim3 grid(C_EMB / GBN, T_SEQ / GBM);
        gemm_tf32<<<grid, 256>>>(att, wpt, b_proj, out, T_SEQ, C_EMB, C_EMB);
    }
}